// round 13
// baseline (speedup 1.0000x reference)
#include <cuda_runtime.h>
#include <cuda_fp16.h>
#include <cstdint>

// ---------------------------------------------------------------------------
// LocalSimilarity: B=8, N=32, C=768, P=16, T=256, K=5
// R13: sim reverted to R11's best shape (64x256 CTA, 2/SM); post+finalize
// fused into one per-batch kernel. fp16 Markidis 3-term HMMA + compaction.
// ---------------------------------------------------------------------------

#define B_      8
#define N_      32
#define C_      768
#define T_      256
#define K_TOP   5
#define SIM_THR 0.05f

#define KC      32
#define NCHK    (C_ / KC)
#define MR      64

#define AOFF(q) ((q) * 4096)
#define BOFF(q) (8192 + (q) * 16384)
#define STAGE_BYTES 40960
#define SMEM_DYN (2 * STAGE_BYTES)

// ---------------- scratch (device globals; no allocation allowed) ----------
__device__ __half g_A1[B_ * T_ * C_];
__device__ __half g_A2[B_ * T_ * C_];
__device__ __half g_B1[(size_t)B_ * N_ * T_ * C_];
__device__ __half g_B2[(size_t)B_ * N_ * T_ * C_];
__device__ float g_invs[B_ * N_ * T_];
__device__ float g_invt[B_ * T_];
__device__ int   g_sidx[B_ * N_ * T_];
__device__ int   g_tidx[B_ * T_];
__device__ int   g_ns[B_ * N_];
__device__ int   g_nt[B_];
__device__ unsigned long long g_rowmax[B_ * N_ * T_];
__device__ unsigned long long g_colmax[B_ * N_ * T_];

// ---------------- PTX helpers ----------------------------------------------
#define LDSM_X4(r0, r1, r2, r3, addr) \
    asm volatile("ldmatrix.sync.aligned.m8n8.x4.shared.b16 {%0,%1,%2,%3}, [%4];" \
        : "=r"(r0), "=r"(r1), "=r"(r2), "=r"(r3) : "r"(addr))

#define MMA16816(d, a, b) \
    asm volatile("mma.sync.aligned.m16n8k16.row.col.f32.f16.f16.f32 " \
        "{%0,%1,%2,%3}, {%4,%5,%6,%7}, {%8,%9}, {%0,%1,%2,%3};" \
        : "+f"((d)[0]), "+f"((d)[1]), "+f"((d)[2]), "+f"((d)[3]) \
        : "r"((a)[0]), "r"((a)[1]), "r"((a)[2]), "r"((a)[3]), \
          "r"((b)[0]), "r"((b)[1]))

__device__ __forceinline__ void cpa16(uint32_t dst, const void* src) {
    asm volatile("cp.async.cg.shared.global [%0], [%1], 16;"
                 :: "r"(dst), "l"(src) : "memory");
}

__device__ __forceinline__ unsigned pack_h2(__half a, __half b) {
    return ((unsigned)__half_as_ushort(b) << 16) | __half_as_ushort(a);
}

// ---------------------------------------------------------------------------
// Kernel 1: transpose (C,T)->(T,C), fp16 hi/lo split, fused inv-norms +
// mask compaction scan + argmax init. grid (B*N + B, T/32), 256 threads.
// (unchanged from R11)
// ---------------------------------------------------------------------------
__global__ void prep_kernel(const float* __restrict__ sf,
                            const float* __restrict__ tf,
                            const float* __restrict__ srcm,
                            const float* __restrict__ tarm) {
    __shared__ float4 buf[2][1024];            // 2 x 16 KB
    __shared__ int spos[T_];
    __shared__ int wtot[8];
    const int blk = blockIdx.x;
    const int t0 = blockIdx.y * 32;
    const int tid = threadIdx.x;
    const int w = tid >> 5, l = tid & 31;
    const int tl = w * 4 + (l >> 3);
    const int cg = l & 7;

    const bool istar = (blk >= B_ * N_);

    {
        const float* m = istar ? (tarm + (blk - B_ * N_) * T_)
                               : (srcm + blk * T_);
        int flag = (m[tid] != 0.f) ? 1 : 0;
        unsigned bal = __ballot_sync(0xffffffffu, flag);
        int wpre = __popc(bal & ((1u << l) - 1u));
        if (l == 31) wtot[w] = __popc(bal);
        __syncthreads();
        int base = 0;
        for (int i = 0; i < w; i++) base += wtot[i];
        int pos = base + wpre;
        spos[tid] = flag ? pos : -1;
        if (blockIdx.y == 0) {
            if (!istar) {
                g_rowmax[blk * T_ + tid] = 0xFFFFull;   // key(0.0f, idx 0)
                g_colmax[blk * T_ + tid] = 0xFFFFull;
                if (flag) g_sidx[blk * T_ + pos] = tid;
                if (tid == 255) g_ns[blk] = pos + flag;
            } else {
                if (flag) g_tidx[(blk - B_ * N_) * T_ + pos] = tid;
                if (tid == 255) g_nt[blk - B_ * N_] = pos + flag;
            }
        }
        __syncthreads();
    }

    const float* src;
    __half *d1, *d2;
    if (!istar) {
        src = sf + (size_t)blk * C_ * T_;
        d1 = g_B1 + (size_t)blk * T_ * C_;
        d2 = g_B2 + (size_t)blk * T_ * C_;
    } else {
        int b = blk - B_ * N_;
        src = tf + (size_t)b * C_ * T_;
        d1 = g_A1 + (size_t)b * T_ * C_;
        d2 = g_A2 + (size_t)b * T_ * C_;
    }
    const int p = spos[t0 + tl];

    const uint32_t smb = (uint32_t)__cvta_generic_to_shared(&buf[0][0]);

#define PLOAD(it, s) do { \
    _Pragma("unroll") \
    for (int _k = 0; _k < 4; _k++) { \
        int _task = tid + _k * 256; \
        int _c = _task >> 3, _t4 = _task & 7; \
        uint32_t _dst = smb + (s) * 16384 + \
            ((_c << 3) + (_t4 ^ ((_c >> 3) & 7))) * 16; \
        cpa16(_dst, src + (size_t)((it) * 128 + _c) * T_ + t0 + _t4 * 4); \
    } \
    asm volatile("cp.async.commit_group;" ::: "memory"); \
} while (0)

    PLOAD(0, 0);
    float ssq = 0.f;

    for (int it = 0; it < 6; it++) {
        if (it + 1 < 6) {
            PLOAD(it + 1, (it + 1) & 1);
            asm volatile("cp.async.wait_group 1;" ::: "memory");
        } else {
            asm volatile("cp.async.wait_group 0;" ::: "memory");
        }
        __syncthreads();
        const float* tilef = (const float*)&buf[it & 1][0];
#pragma unroll
        for (int half = 0; half < 2; half++) {
            unsigned hi[4], lo[4];
#pragma unroll
            for (int i = 0; i < 8; i += 2) {
                int c = half * 64 + cg * 8 + i;
                int g = (c >> 3) & 7;
                float x0 = tilef[c * 32 + (((tl >> 2) ^ g) << 2) + (tl & 3)];
                float x1 = tilef[(c + 1) * 32 + (((tl >> 2) ^ g) << 2) + (tl & 3)];
                ssq = fmaf(x0, x0, fmaf(x1, x1, ssq));
                __half h0 = __float2half_rn(x0), h1 = __float2half_rn(x1);
                hi[i >> 1] = pack_h2(h0, h1);
                lo[i >> 1] = pack_h2(__float2half_rn(x0 - __half2float(h0)),
                                     __float2half_rn(x1 - __half2float(h1)));
            }
            if (p >= 0) {
                size_t oidx = (size_t)p * C_ + it * 128 + half * 64 + cg * 8;
                *(uint4*)(d1 + oidx) = make_uint4(hi[0], hi[1], hi[2], hi[3]);
                *(uint4*)(d2 + oidx) = make_uint4(lo[0], lo[1], lo[2], lo[3]);
            }
        }
        __syncthreads();
    }
#pragma unroll
    for (int off = 1; off < 8; off <<= 1)
        ssq += __shfl_xor_sync(0xffffffffu, ssq, off);
    if (cg == 0) {
        float inv = 1.f / fmaxf(sqrtf(ssq), 1e-12f);
        if (!istar) g_invs[blk * T_ + t0 + tl] = inv;
        else        g_invt[(blk - B_ * N_) * T_ + t0 + tl] = inv;
    }
}

// ---------------------------------------------------------------------------
// Kernel 2: HMMA sim on COMPACTED rows/cols. grid (B*N, 4), 256 threads,
// warp grid 2(M) x 4(N); col groups of 16 round-robin over warps.
// (unchanged from R11 — best measured shape)
// ---------------------------------------------------------------------------
__global__ __launch_bounds__(256, 2)
void sim_hmma_kernel() {
    extern __shared__ __align__(1024) char dsm[];
    __shared__ float cs_c[T_];
    __shared__ float rs_c[MR];
    __shared__ int   sidx_s[T_];
    __shared__ int   tidx_s[MR];

    const int tid = threadIdx.x;
    const int w = tid >> 5, l = tid & 31;
    const int wm = w >> 2;
    const int wn = w & 3;
    const int bn = blockIdx.x, b = bn >> 5;
    const int trow0 = blockIdx.y * MR;

    const int Nt = g_nt[b], Ns = g_ns[bn];
    if (trow0 >= Nt || Ns == 0) return;
    const int G = (Ns + 15) >> 4;
    const int G16 = G << 4;

    const uint32_t smbase = (uint32_t)__cvta_generic_to_shared(dsm);

    if (tid < MR) {
        int i = min(trow0 + tid, Nt - 1);
        int tr = g_tidx[b * T_ + i];
        tidx_s[tid] = tr;
        rs_c[tid] = g_invt[b * T_ + tr];
    }
    {
        int j = min(tid, Ns - 1);
        int sr = g_sidx[bn * T_ + j];
        sidx_s[tid] = sr;
        cs_c[tid] = g_invs[bn * T_ + sr];
    }
    __syncthreads();

    const char* aArr[2] = {
        (const char*)(g_A1 + (size_t)b * T_ * C_),
        (const char*)(g_A2 + (size_t)b * T_ * C_) };
    const char* bArr[2] = {
        (const char*)(g_B1 + (size_t)bn * T_ * C_),
        (const char*)(g_B2 + (size_t)bn * T_ * C_) };

    const int m8 = l >> 3, r8 = l & 7;
    const int kaA = m8 >> 1;
    const int kaB = m8 & 1;
    uint32_t aoff[2]; int sAx[2];
#pragma unroll
    for (int mi = 0; mi < 2; mi++) {
        int rowA = wm * 32 + mi * 16 + (m8 & 1) * 8 + r8;
        aoff[mi] = rowA * 64; sAx[mi] = (rowA >> 1) & 3;
    }
    uint32_t bofs[4]; int sBx[4]; int gact[4];
#pragma unroll
    for (int slot = 0; slot < 4; slot++) {
        int g = slot * 4 + wn;
        gact[slot] = (g < G);
        int rowB = g * 16 + (m8 >> 1) * 8 + r8;
        bofs[slot] = rowB * 64;
        sBx[slot] = (rowB >> 1) & 3;
    }

#define LOADCHUNK(ck, stg) do { \
    uint32_t _sb = smbase + (stg) * STAGE_BYTES; \
    const int _ntask = 128 + 2 * G16; \
    for (int _task = tid; _task < _ntask; _task += 256) { \
        const char* _gp; uint32_t _dst; int _s; \
        if (_task < 128) { \
            int _q = _task >> 6; int _row = _task & 63; \
            int _pr = min(trow0 + _row, Nt - 1); \
            _gp = ((_q == 0) ? aArr[0] : aArr[1]) + \
                  (size_t)_pr * (C_ * 2) + (ck) * 64; \
            _dst = _sb + AOFF(_q) + _row * 64; \
            _s = (_row >> 1) & 3; \
        } else { \
            int _t2 = _task - 128; \
            int _q = (_t2 >= G16) ? 1 : 0; \
            int _row = _t2 - _q * G16; \
            int _br = min(_row, Ns - 1); \
            _gp = ((_q == 0) ? bArr[0] : bArr[1]) + \
                  (size_t)_br * (C_ * 2) + (ck) * 64; \
            _dst = _sb + BOFF(_q) + _row * 64; \
            _s = (_row >> 1) & 3; \
        } \
        _Pragma("unroll") \
        for (int _g = 0; _g < 4; _g++) \
            cpa16(_dst + ((_g ^ _s) << 4), _gp + _g * 16); \
    } \
} while (0)

    float acc[2][8][4];
#pragma unroll
    for (int mi = 0; mi < 2; mi++)
#pragma unroll
        for (int ni = 0; ni < 8; ni++)
#pragma unroll
            for (int e = 0; e < 4; e++) acc[mi][ni][e] = 0.f;

    LOADCHUNK(0, 0);
    asm volatile("cp.async.commit_group;" ::: "memory");

    for (int ck = 0; ck < NCHK; ck++) {
        if (ck + 1 < NCHK) LOADCHUNK(ck + 1, (ck + 1) & 1);
        asm volatile("cp.async.commit_group;" ::: "memory");
        asm volatile("cp.async.wait_group 1;" ::: "memory");
        __syncthreads();

        const uint32_t st = smbase + (ck & 1) * STAGE_BYTES;
#pragma unroll
        for (int step = 0; step < 2; step++) {
            const int kg0 = step * 2;
            uint32_t afr[2][2][4];
#pragma unroll
            for (int q = 0; q < 2; q++)
#pragma unroll
                for (int mi = 0; mi < 2; mi++) {
                    uint32_t adr = st + AOFF(q) + aoff[mi] +
                                   (((kg0 + kaA) ^ sAx[mi]) << 4);
                    LDSM_X4(afr[q][mi][0], afr[q][mi][1],
                            afr[q][mi][2], afr[q][mi][3], adr);
                }
#pragma unroll
            for (int bi = 0; bi < 2; bi++) {
#pragma unroll
                for (int slot = 0; slot < 4; slot++) {
                    if (!gact[slot]) continue;
                    uint32_t bfr[2][2];
                    {
                        uint32_t adr = st + BOFF(bi) + bofs[slot] +
                                       (((kg0 + kaB) ^ sBx[slot]) << 4);
                        uint32_t r0, r1, r2, r3;
                        LDSM_X4(r0, r1, r2, r3, adr);
                        bfr[0][0] = r0; bfr[0][1] = r1;
                        bfr[1][0] = r2; bfr[1][1] = r3;
                    }
                    const int na = 2 - bi;
#pragma unroll
                    for (int ai = 0; ai < 2; ai++) {
                        if (ai >= na) break;
#pragma unroll
                        for (int mi = 0; mi < 2; mi++)
#pragma unroll
                            for (int ih = 0; ih < 2; ih++)
                                MMA16816(acc[mi][slot * 2 + ih],
                                         afr[ai][mi], bfr[ih]);
                    }
                }
            }
        }
        __syncthreads();
    }

    // ---- epilogue ----
#pragma unroll
    for (int mi = 0; mi < 2; mi++)
#pragma unroll
        for (int half = 0; half < 2; half++) {
            const int rl = wm * 32 + mi * 16 + (l >> 2) + half * 8;
            const float rv = rs_c[rl];
            float best = 0.f; int bc = 0;
#pragma unroll
            for (int slot = 0; slot < 4; slot++) {
                if (!gact[slot]) continue;
#pragma unroll
                for (int ih = 0; ih < 2; ih++)
#pragma unroll
                    for (int e = 0; e < 2; e++) {
                        int c = (slot * 4 + wn) * 16 + ih * 8 + 2 * (l & 3) + e;
                        float v = acc[mi][slot * 2 + ih][half * 2 + e] * rv *
                                  cs_c[min(c, Ns - 1)];
                        if (v < SIM_THR) v = 0.f;
                        acc[mi][slot * 2 + ih][half * 2 + e] = v;
                        if (v > best) { best = v; bc = c; }
                    }
            }
#pragma unroll
            for (int off = 1; off <= 2; off <<= 1) {
                float ov = __shfl_xor_sync(0xffffffffu, best, off);
                int   oc = __shfl_xor_sync(0xffffffffu, bc, off);
                if (ov > best || (ov == best && oc < bc)) { best = ov; bc = oc; }
            }
            if ((l & 3) == 0 && best > 0.f && trow0 + rl < Nt) {
                int rr = tidx_s[rl];
                int sr = sidx_s[min(bc, Ns - 1)];
                atomicMax(&g_rowmax[bn * T_ + rr],
                    ((unsigned long long)__float_as_uint(best) << 32) |
                    (unsigned)(65535 - sr));
            }
        }
#pragma unroll
    for (int slot = 0; slot < 4; slot++) {
        if (!gact[slot]) continue;
#pragma unroll
        for (int ih = 0; ih < 2; ih++)
#pragma unroll
            for (int e = 0; e < 2; e++) {
                unsigned long long key = 0ull;
#pragma unroll
                for (int mi = 0; mi < 2; mi++)
#pragma unroll
                    for (int half = 0; half < 2; half++) {
                        int rl = wm * 32 + mi * 16 + (l >> 2) + half * 8;
                        int rr = tidx_s[rl];
                        unsigned long long k2 =
                            ((unsigned long long)__float_as_uint(
                                acc[mi][slot * 2 + ih][half * 2 + e]) << 32) |
                            (unsigned)(65535 - rr);
                        if (k2 > key) key = k2;
                    }
#pragma unroll
                for (int off = 4; off <= 16; off <<= 1) {
                    unsigned long long o = __shfl_xor_sync(0xffffffffu, key, off);
                    if (o > key) key = o;
                }
                if (l < 4 && (key >> 32) != 0ull) {
                    int c = (slot * 4 + wn) * 16 + ih * 8 + 2 * l + e;
                    if (c < Ns)
                        atomicMax(&g_colmax[bn * T_ + sidx_s[c]], key);
                }
            }
    }
}

// ---------------------------------------------------------------------------
// Kernel 3: fused post + finalize. grid B, 256 threads.
// Per n: cycle consistency + masks (kept in registers per thread t=tid, one
// n at a time), block-reduce mc/avg into smem; then top-5; then write output.
// ---------------------------------------------------------------------------
__global__ void tail_kernel(const float* __restrict__ srcm,
                            const float* __restrict__ tarm,
                            float* __restrict__ out) {
    __shared__ float s_avg[N_];
    __shared__ float s_mc[N_];
    __shared__ float s_score[N_ * 8];   // reused as per-n warp sums
    __shared__ int   sid[K_TOP];
    __shared__ float sval[K_TOP];
    // per-n stored results (score/mask/idx) kept in global is avoided:
    // store per-n slices in smem: 32 n x 256 t won't fit; instead keep
    // per-thread (t=tid) values for ALL n in registers via arrays of 32?
    // 32*3 regs too much -> recompute selected slices after top-5 (cheap).
    __shared__ float wsum1[8], wsum2[8];

    const int b = blockIdx.x;
    const int tid = threadIdx.x;
    const int w = tid >> 5, l = tid & 31;
    const int t = tid;
    const float tmv = tarm[b * T_ + t];

    for (int n = 0; n < N_; n++) {
        const int bn = b * N_ + n;
        unsigned long long rm = g_rowmax[bn * T_ + t];
        float st = __uint_as_float((unsigned)(rm >> 32));
        int   it = 65535 - (int)(unsigned)(rm & 0xFFFFFFFFull);
        unsigned long long cm_it = g_colmax[bn * T_ + it];
        unsigned long long cm_t  = g_colmax[bn * T_ + t];
        int idx_s2t_t = 65535 - (int)(unsigned)(cm_t & 0xFFFFFFFFull);
        float sc_s2t  = __uint_as_float((unsigned)(cm_it >> 32));
        int idx_s2s   = 65535 - (int)(unsigned)(cm_it & 0xFFFFFFFFull);

        bool msim = (st >= SIM_THR);
        int dx = (idx_s2s & 15) - (t & 15);
        int dy = (idx_s2s >> 4) - (t >> 4);
        bool mcyc = (dx * dx + dy * dy <= 4) && (sc_s2t >= SIM_THR);

        float mall = 0.f;
        if (msim && mcyc) {
            float mt2s = srcm[bn * T_ + it];
            mall = tmv * mt2s * ((idx_s2t_t != 0) ? 1.f : 0.f)
                             * ((it != 0) ? 1.f : 0.f);
        }
        float s1 = mall, s2 = st * mall;
#pragma unroll
        for (int off = 16; off; off >>= 1) {
            s1 += __shfl_xor_sync(0xffffffffu, s1, off);
            s2 += __shfl_xor_sync(0xffffffffu, s2, off);
        }
        if (l == 0) { wsum1[w] = s1; wsum2[w] = s2; }
        __syncthreads();
        if (tid == 0) {
            float mc = 0.f, ss = 0.f;
            for (int wi = 0; wi < 8; wi++) { mc += wsum1[wi]; ss += wsum2[wi]; }
            s_mc[n]  = mc;
            s_avg[n] = (mc > 0.f) ? ss / (float)T_ : 0.f;
        }
        __syncthreads();
    }

    if (tid == 0) {
        bool used[N_];
        for (int n = 0; n < N_; n++) used[n] = false;
        for (int k = 0; k < K_TOP; k++) {
            float best = -1.f; int bi = 0; bool found = false;
            for (int n = 0; n < N_; n++) {
                float v = s_avg[n];
                if (!used[n] && (!found || v > best)) {
                    best = v; bi = n; found = true;
                }
            }
            used[bi] = true; sid[k] = bi; sval[k] = best;
        }
    }
    __syncthreads();

    const int OFF_SP   = 2 * B_ * K_TOP;
    const int OFF_TP   = OFF_SP + B_ * K_TOP * T_;
    const int OFF_SRCP = OFF_TP + B_ * K_TOP * T_ * 2;
    const int OFF_MC   = OFF_SRCP + B_ * K_TOP * T_ * 2;

    if (tid < K_TOP) {
        out[b * K_TOP + tid] = (float)sid[tid];
        out[B_ * K_TOP + b * K_TOP + tid] = sval[tid];
    }
    if (tid < N_) out[OFF_MC + b * N_ + tid] = s_mc[tid];

#pragma unroll
    for (int k = 0; k < K_TOP; k++) {
        const int bn = b * N_ + sid[k];
        unsigned long long rm = g_rowmax[bn * T_ + t];
        float st = __uint_as_float((unsigned)(rm >> 32));
        int   it = 65535 - (int)(unsigned)(rm & 0xFFFFFFFFull);
        unsigned long long cm_it = g_colmax[bn * T_ + it];
        unsigned long long cm_t  = g_colmax[bn * T_ + t];
        int idx_s2t_t = 65535 - (int)(unsigned)(cm_t & 0xFFFFFFFFull);
        float sc_s2t  = __uint_as_float((unsigned)(cm_it >> 32));
        int idx_s2s   = 65535 - (int)(unsigned)(cm_it & 0xFFFFFFFFull);

        bool msim = (st >= SIM_THR);
        int dx = (idx_s2s & 15) - (t & 15);
        int dy = (idx_s2s >> 4) - (t >> 4);
        bool mcyc = (dx * dx + dy * dy <= 4) && (sc_s2t >= SIM_THR);
        float mall = 0.f;
        if (msim && mcyc) {
            float mt2s = srcm[bn * T_ + it];
            mall = tmv * mt2s * ((idx_s2t_t != 0) ? 1.f : 0.f)
                             * ((it != 0) ? 1.f : 0.f);
        }
        int base = (b * K_TOP + k) * T_ + t;
        out[OFF_SP + base] = st;
        bool nz = (mall != 0.f);
        out[OFF_TP + base * 2 + 0]   = nz ? (float)(t & 15)  : -1.f;
        out[OFF_TP + base * 2 + 1]   = nz ? (float)(t >> 4)  : -1.f;
        out[OFF_SRCP + base * 2 + 0] = nz ? (float)(it & 15) : -1.f;
        out[OFF_SRCP + base * 2 + 1] = nz ? (float)(it >> 4) : -1.f;
    }
}

// ---------------------------------------------------------------------------
extern "C" void kernel_launch(void* const* d_in, const int* in_sizes, int n_in,
                              void* d_out, int out_size) {
    const float* sf   = (const float*)d_in[0];  // (B,N,C,P,P)
    const float* tf   = (const float*)d_in[1];  // (B,C,P,P)
    const float* srcm = (const float*)d_in[2];  // (B,N,P,P)
    const float* tarm = (const float*)d_in[3];  // (B,P,P)

    cudaFuncSetAttribute(sim_hmma_kernel,
                         cudaFuncAttributeMaxDynamicSharedMemorySize, SMEM_DYN);

    dim3 gp(B_ * N_ + B_, T_ / 32);
    prep_kernel<<<gp, 256>>>(sf, tf, srcm, tarm);
    dim3 gs(B_ * N_, 4);
    sim_hmma_kernel<<<gs, 256, SMEM_DYN>>>();
    tail_kernel<<<B_, 256>>>(srcm, tarm, (float*)d_out);
}

// round 15
// speedup vs baseline: 1.1227x; 1.1227x over previous
#include <cuda_runtime.h>
#include <cuda_fp16.h>
#include <cstdint>

// ---------------------------------------------------------------------------
// LocalSimilarity: B=8, N=32, C=768, P=16, T=256, K=5
// R14: best measured pieces recombined — prep (R11/R13, 55us @71% DRAM),
// sim (R11 shape, 64x256 CTA, 2/SM), post (R11, 256 CTAs), finalize
// (R12 parallel, grid (B,K)). fp16 Markidis 3-term HMMA + mask compaction.
// ---------------------------------------------------------------------------

#define B_      8
#define N_      32
#define C_      768
#define T_      256
#define K_TOP   5
#define SIM_THR 0.05f

#define KC      32
#define NCHK    (C_ / KC)
#define MR      64

#define AOFF(q) ((q) * 4096)
#define BOFF(q) (8192 + (q) * 16384)
#define STAGE_BYTES 40960
#define SMEM_DYN (2 * STAGE_BYTES)

// ---------------- scratch (device globals; no allocation allowed) ----------
__device__ __half g_A1[B_ * T_ * C_];
__device__ __half g_A2[B_ * T_ * C_];
__device__ __half g_B1[(size_t)B_ * N_ * T_ * C_];
__device__ __half g_B2[(size_t)B_ * N_ * T_ * C_];
__device__ float g_invs[B_ * N_ * T_];
__device__ float g_invt[B_ * T_];
__device__ int   g_sidx[B_ * N_ * T_];
__device__ int   g_tidx[B_ * T_];
__device__ int   g_ns[B_ * N_];
__device__ int   g_nt[B_];
__device__ unsigned long long g_rowmax[B_ * N_ * T_];
__device__ unsigned long long g_colmax[B_ * N_ * T_];
__device__ float g_maskall[B_ * N_ * T_];
__device__ float g_scoret[B_ * N_ * T_];
__device__ int   g_idxt[B_ * N_ * T_];
__device__ float g_avg[B_ * N_];
__device__ float g_mc[B_ * N_];

// ---------------- PTX helpers ----------------------------------------------
#define LDSM_X4(r0, r1, r2, r3, addr) \
    asm volatile("ldmatrix.sync.aligned.m8n8.x4.shared.b16 {%0,%1,%2,%3}, [%4];" \
        : "=r"(r0), "=r"(r1), "=r"(r2), "=r"(r3) : "r"(addr))

#define MMA16816(d, a, b) \
    asm volatile("mma.sync.aligned.m16n8k16.row.col.f32.f16.f16.f32 " \
        "{%0,%1,%2,%3}, {%4,%5,%6,%7}, {%8,%9}, {%0,%1,%2,%3};" \
        : "+f"((d)[0]), "+f"((d)[1]), "+f"((d)[2]), "+f"((d)[3]) \
        : "r"((a)[0]), "r"((a)[1]), "r"((a)[2]), "r"((a)[3]), \
          "r"((b)[0]), "r"((b)[1]))

__device__ __forceinline__ void cpa16(uint32_t dst, const void* src) {
    asm volatile("cp.async.cg.shared.global [%0], [%1], 16;"
                 :: "r"(dst), "l"(src) : "memory");
}

__device__ __forceinline__ unsigned pack_h2(__half a, __half b) {
    return ((unsigned)__half_as_ushort(b) << 16) | __half_as_ushort(a);
}

// ---------------------------------------------------------------------------
// Kernel 1: transpose (C,T)->(T,C), fp16 hi/lo split, fused inv-norms +
// mask compaction scan + argmax init. grid (B*N + B, T/32), 256 threads.
// ---------------------------------------------------------------------------
__global__ void prep_kernel(const float* __restrict__ sf,
                            const float* __restrict__ tf,
                            const float* __restrict__ srcm,
                            const float* __restrict__ tarm) {
    __shared__ float4 buf[2][1024];            // 2 x 16 KB
    __shared__ int spos[T_];
    __shared__ int wtot[8];
    const int blk = blockIdx.x;
    const int t0 = blockIdx.y * 32;
    const int tid = threadIdx.x;
    const int w = tid >> 5, l = tid & 31;
    const int tl = w * 4 + (l >> 3);
    const int cg = l & 7;

    const bool istar = (blk >= B_ * N_);

    {
        const float* m = istar ? (tarm + (blk - B_ * N_) * T_)
                               : (srcm + blk * T_);
        int flag = (m[tid] != 0.f) ? 1 : 0;
        unsigned bal = __ballot_sync(0xffffffffu, flag);
        int wpre = __popc(bal & ((1u << l) - 1u));
        if (l == 31) wtot[w] = __popc(bal);
        __syncthreads();
        int base = 0;
        for (int i = 0; i < w; i++) base += wtot[i];
        int pos = base + wpre;
        spos[tid] = flag ? pos : -1;
        if (blockIdx.y == 0) {
            if (!istar) {
                g_rowmax[blk * T_ + tid] = 0xFFFFull;   // key(0.0f, idx 0)
                g_colmax[blk * T_ + tid] = 0xFFFFull;
                if (flag) g_sidx[blk * T_ + pos] = tid;
                if (tid == 255) g_ns[blk] = pos + flag;
            } else {
                if (flag) g_tidx[(blk - B_ * N_) * T_ + pos] = tid;
                if (tid == 255) g_nt[blk - B_ * N_] = pos + flag;
            }
        }
        __syncthreads();
    }

    const float* src;
    __half *d1, *d2;
    if (!istar) {
        src = sf + (size_t)blk * C_ * T_;
        d1 = g_B1 + (size_t)blk * T_ * C_;
        d2 = g_B2 + (size_t)blk * T_ * C_;
    } else {
        int b = blk - B_ * N_;
        src = tf + (size_t)b * C_ * T_;
        d1 = g_A1 + (size_t)b * T_ * C_;
        d2 = g_A2 + (size_t)b * T_ * C_;
    }
    const int p = spos[t0 + tl];

    const uint32_t smb = (uint32_t)__cvta_generic_to_shared(&buf[0][0]);

#define PLOAD(it, s) do { \
    _Pragma("unroll") \
    for (int _k = 0; _k < 4; _k++) { \
        int _task = tid + _k * 256; \
        int _c = _task >> 3, _t4 = _task & 7; \
        uint32_t _dst = smb + (s) * 16384 + \
            ((_c << 3) + (_t4 ^ ((_c >> 3) & 7))) * 16; \
        cpa16(_dst, src + (size_t)((it) * 128 + _c) * T_ + t0 + _t4 * 4); \
    } \
    asm volatile("cp.async.commit_group;" ::: "memory"); \
} while (0)

    PLOAD(0, 0);
    float ssq = 0.f;

    for (int it = 0; it < 6; it++) {
        if (it + 1 < 6) {
            PLOAD(it + 1, (it + 1) & 1);
            asm volatile("cp.async.wait_group 1;" ::: "memory");
        } else {
            asm volatile("cp.async.wait_group 0;" ::: "memory");
        }
        __syncthreads();
        const float* tilef = (const float*)&buf[it & 1][0];
#pragma unroll
        for (int half = 0; half < 2; half++) {
            unsigned hi[4], lo[4];
#pragma unroll
            for (int i = 0; i < 8; i += 2) {
                int c = half * 64 + cg * 8 + i;
                int g = (c >> 3) & 7;
                float x0 = tilef[c * 32 + (((tl >> 2) ^ g) << 2) + (tl & 3)];
                float x1 = tilef[(c + 1) * 32 + (((tl >> 2) ^ g) << 2) + (tl & 3)];
                ssq = fmaf(x0, x0, fmaf(x1, x1, ssq));
                __half h0 = __float2half_rn(x0), h1 = __float2half_rn(x1);
                hi[i >> 1] = pack_h2(h0, h1);
                lo[i >> 1] = pack_h2(__float2half_rn(x0 - __half2float(h0)),
                                     __float2half_rn(x1 - __half2float(h1)));
            }
            if (p >= 0) {
                size_t oidx = (size_t)p * C_ + it * 128 + half * 64 + cg * 8;
                *(uint4*)(d1 + oidx) = make_uint4(hi[0], hi[1], hi[2], hi[3]);
                *(uint4*)(d2 + oidx) = make_uint4(lo[0], lo[1], lo[2], lo[3]);
            }
        }
        __syncthreads();
    }
#pragma unroll
    for (int off = 1; off < 8; off <<= 1)
        ssq += __shfl_xor_sync(0xffffffffu, ssq, off);
    if (cg == 0) {
        float inv = 1.f / fmaxf(sqrtf(ssq), 1e-12f);
        if (!istar) g_invs[blk * T_ + t0 + tl] = inv;
        else        g_invt[(blk - B_ * N_) * T_ + t0 + tl] = inv;
    }
}

// ---------------------------------------------------------------------------
// Kernel 2: HMMA sim on COMPACTED rows/cols. grid (B*N, 4), 256 threads,
// warp grid 2(M) x 4(N); col groups of 16 round-robin over warps.
// (R11's best measured shape, unchanged)
// ---------------------------------------------------------------------------
__global__ __launch_bounds__(256, 2)
void sim_hmma_kernel() {
    extern __shared__ __align__(1024) char dsm[];
    __shared__ float cs_c[T_];
    __shared__ float rs_c[MR];
    __shared__ int   sidx_s[T_];
    __shared__ int   tidx_s[MR];

    const int tid = threadIdx.x;
    const int w = tid >> 5, l = tid & 31;
    const int wm = w >> 2;
    const int wn = w & 3;
    const int bn = blockIdx.x, b = bn >> 5;
    const int trow0 = blockIdx.y * MR;

    const int Nt = g_nt[b], Ns = g_ns[bn];
    if (trow0 >= Nt || Ns == 0) return;
    const int G = (Ns + 15) >> 4;
    const int G16 = G << 4;

    const uint32_t smbase = (uint32_t)__cvta_generic_to_shared(dsm);

    if (tid < MR) {
        int i = min(trow0 + tid, Nt - 1);
        int tr = g_tidx[b * T_ + i];
        tidx_s[tid] = tr;
        rs_c[tid] = g_invt[b * T_ + tr];
    }
    {
        int j = min(tid, Ns - 1);
        int sr = g_sidx[bn * T_ + j];
        sidx_s[tid] = sr;
        cs_c[tid] = g_invs[bn * T_ + sr];
    }
    __syncthreads();

    const char* aArr[2] = {
        (const char*)(g_A1 + (size_t)b * T_ * C_),
        (const char*)(g_A2 + (size_t)b * T_ * C_) };
    const char* bArr[2] = {
        (const char*)(g_B1 + (size_t)bn * T_ * C_),
        (const char*)(g_B2 + (size_t)bn * T_ * C_) };

    const int m8 = l >> 3, r8 = l & 7;
    const int kaA = m8 >> 1;
    const int kaB = m8 & 1;
    uint32_t aoff[2]; int sAx[2];
#pragma unroll
    for (int mi = 0; mi < 2; mi++) {
        int rowA = wm * 32 + mi * 16 + (m8 & 1) * 8 + r8;
        aoff[mi] = rowA * 64; sAx[mi] = (rowA >> 1) & 3;
    }
    uint32_t bofs[4]; int sBx[4]; int gact[4];
#pragma unroll
    for (int slot = 0; slot < 4; slot++) {
        int g = slot * 4 + wn;
        gact[slot] = (g < G);
        int rowB = g * 16 + (m8 >> 1) * 8 + r8;
        bofs[slot] = rowB * 64;
        sBx[slot] = (rowB >> 1) & 3;
    }

#define LOADCHUNK(ck, stg) do { \
    uint32_t _sb = smbase + (stg) * STAGE_BYTES; \
    const int _ntask = 128 + 2 * G16; \
    for (int _task = tid; _task < _ntask; _task += 256) { \
        const char* _gp; uint32_t _dst; int _s; \
        if (_task < 128) { \
            int _q = _task >> 6; int _row = _task & 63; \
            int _pr = min(trow0 + _row, Nt - 1); \
            _gp = ((_q == 0) ? aArr[0] : aArr[1]) + \
                  (size_t)_pr * (C_ * 2) + (ck) * 64; \
            _dst = _sb + AOFF(_q) + _row * 64; \
            _s = (_row >> 1) & 3; \
        } else { \
            int _t2 = _task - 128; \
            int _q = (_t2 >= G16) ? 1 : 0; \
            int _row = _t2 - _q * G16; \
            int _br = min(_row, Ns - 1); \
            _gp = ((_q == 0) ? bArr[0] : bArr[1]) + \
                  (size_t)_br * (C_ * 2) + (ck) * 64; \
            _dst = _sb + BOFF(_q) + _row * 64; \
            _s = (_row >> 1) & 3; \
        } \
        _Pragma("unroll") \
        for (int _g = 0; _g < 4; _g++) \
            cpa16(_dst + ((_g ^ _s) << 4), _gp + _g * 16); \
    } \
} while (0)

    float acc[2][8][4];
#pragma unroll
    for (int mi = 0; mi < 2; mi++)
#pragma unroll
        for (int ni = 0; ni < 8; ni++)
#pragma unroll
            for (int e = 0; e < 4; e++) acc[mi][ni][e] = 0.f;

    LOADCHUNK(0, 0);
    asm volatile("cp.async.commit_group;" ::: "memory");

    for (int ck = 0; ck < NCHK; ck++) {
        if (ck + 1 < NCHK) LOADCHUNK(ck + 1, (ck + 1) & 1);
        asm volatile("cp.async.commit_group;" ::: "memory");
        asm volatile("cp.async.wait_group 1;" ::: "memory");
        __syncthreads();

        const uint32_t st = smbase + (ck & 1) * STAGE_BYTES;
#pragma unroll
        for (int step = 0; step < 2; step++) {
            const int kg0 = step * 2;
            uint32_t afr[2][2][4];
#pragma unroll
            for (int q = 0; q < 2; q++)
#pragma unroll
                for (int mi = 0; mi < 2; mi++) {
                    uint32_t adr = st + AOFF(q) + aoff[mi] +
                                   (((kg0 + kaA) ^ sAx[mi]) << 4);
                    LDSM_X4(afr[q][mi][0], afr[q][mi][1],
                            afr[q][mi][2], afr[q][mi][3], adr);
                }
#pragma unroll
            for (int bi = 0; bi < 2; bi++) {
#pragma unroll
                for (int slot = 0; slot < 4; slot++) {
                    if (!gact[slot]) continue;
                    uint32_t bfr[2][2];
                    {
                        uint32_t adr = st + BOFF(bi) + bofs[slot] +
                                       (((kg0 + kaB) ^ sBx[slot]) << 4);
                        uint32_t r0, r1, r2, r3;
                        LDSM_X4(r0, r1, r2, r3, adr);
                        bfr[0][0] = r0; bfr[0][1] = r1;
                        bfr[1][0] = r2; bfr[1][1] = r3;
                    }
                    const int na = 2 - bi;
#pragma unroll
                    for (int ai = 0; ai < 2; ai++) {
                        if (ai >= na) break;
#pragma unroll
                        for (int mi = 0; mi < 2; mi++)
#pragma unroll
                            for (int ih = 0; ih < 2; ih++)
                                MMA16816(acc[mi][slot * 2 + ih],
                                         afr[ai][mi], bfr[ih]);
                    }
                }
            }
        }
        __syncthreads();
    }

    // ---- epilogue ----
#pragma unroll
    for (int mi = 0; mi < 2; mi++)
#pragma unroll
        for (int half = 0; half < 2; half++) {
            const int rl = wm * 32 + mi * 16 + (l >> 2) + half * 8;
            const float rv = rs_c[rl];
            float best = 0.f; int bc = 0;
#pragma unroll
            for (int slot = 0; slot < 4; slot++) {
                if (!gact[slot]) continue;
#pragma unroll
                for (int ih = 0; ih < 2; ih++)
#pragma unroll
                    for (int e = 0; e < 2; e++) {
                        int c = (slot * 4 + wn) * 16 + ih * 8 + 2 * (l & 3) + e;
                        float v = acc[mi][slot * 2 + ih][half * 2 + e] * rv *
                                  cs_c[min(c, Ns - 1)];
                        if (v < SIM_THR) v = 0.f;
                        acc[mi][slot * 2 + ih][half * 2 + e] = v;
                        if (v > best) { best = v; bc = c; }
                    }
            }
#pragma unroll
            for (int off = 1; off <= 2; off <<= 1) {
                float ov = __shfl_xor_sync(0xffffffffu, best, off);
                int   oc = __shfl_xor_sync(0xffffffffu, bc, off);
                if (ov > best || (ov == best && oc < bc)) { best = ov; bc = oc; }
            }
            if ((l & 3) == 0 && best > 0.f && trow0 + rl < Nt) {
                int rr = tidx_s[rl];
                int sr = sidx_s[min(bc, Ns - 1)];
                atomicMax(&g_rowmax[bn * T_ + rr],
                    ((unsigned long long)__float_as_uint(best) << 32) |
                    (unsigned)(65535 - sr));
            }
        }
#pragma unroll
    for (int slot = 0; slot < 4; slot++) {
        if (!gact[slot]) continue;
#pragma unroll
        for (int ih = 0; ih < 2; ih++)
#pragma unroll
            for (int e = 0; e < 2; e++) {
                unsigned long long key = 0ull;
#pragma unroll
                for (int mi = 0; mi < 2; mi++)
#pragma unroll
                    for (int half = 0; half < 2; half++) {
                        int rl = wm * 32 + mi * 16 + (l >> 2) + half * 8;
                        int rr = tidx_s[rl];
                        unsigned long long k2 =
                            ((unsigned long long)__float_as_uint(
                                acc[mi][slot * 2 + ih][half * 2 + e]) << 32) |
                            (unsigned)(65535 - rr);
                        if (k2 > key) key = k2;
                    }
#pragma unroll
                for (int off = 4; off <= 16; off <<= 1) {
                    unsigned long long o = __shfl_xor_sync(0xffffffffu, key, off);
                    if (o > key) key = o;
                }
                if (l < 4 && (key >> 32) != 0ull) {
                    int c = (slot * 4 + wn) * 16 + ih * 8 + 2 * l + e;
                    if (c < Ns)
                        atomicMax(&g_colmax[bn * T_ + sidx_s[c]], key);
                }
            }
    }
}

// ---------------------------------------------------------------------------
// Kernel 3: per-(b,n) cycle consistency + masks. grid B*N, 256 threads.
// ---------------------------------------------------------------------------
__global__ void post_kernel(const float* __restrict__ srcm,
                            const float* __restrict__ tarm) {
    __shared__ float wsum1[8], wsum2[8];
    const int bn = blockIdx.x, b = bn >> 5;
    const int tid = threadIdx.x;
    const int w = tid >> 5, l = tid & 31;

    int t = tid;
    unsigned long long rm = g_rowmax[bn * T_ + t];
    float st = __uint_as_float((unsigned)(rm >> 32));
    int   it = 65535 - (int)(unsigned)(rm & 0xFFFFFFFFull);
    unsigned long long cm_t  = g_colmax[bn * T_ + t];
    unsigned long long cm_it = g_colmax[bn * T_ + it];
    int idx_s2t_t = 65535 - (int)(unsigned)(cm_t & 0xFFFFFFFFull);
    float sc_s2t  = __uint_as_float((unsigned)(cm_it >> 32));
    int idx_s2s   = 65535 - (int)(unsigned)(cm_it & 0xFFFFFFFFull);

    bool msim = (st >= SIM_THR);
    int dx = (idx_s2s & 15) - (t & 15);
    int dy = (idx_s2s >> 4) - (t >> 4);
    bool mcyc = (dx * dx + dy * dy <= 4) && (sc_s2t >= SIM_THR);

    float mall = 0.f;
    if (msim && mcyc) {
        float mt2s = srcm[bn * T_ + it];
        float tm   = tarm[b * T_ + t];
        mall = tm * mt2s * ((idx_s2t_t != 0) ? 1.f : 0.f)
                         * ((it != 0) ? 1.f : 0.f);
    }
    g_maskall[bn * T_ + t] = mall;
    g_scoret[bn * T_ + t]  = st;
    g_idxt[bn * T_ + t]    = it;

    float s1 = mall, s2 = st * mall;
#pragma unroll
    for (int off = 16; off; off >>= 1) {
        s1 += __shfl_xor_sync(0xffffffffu, s1, off);
        s2 += __shfl_xor_sync(0xffffffffu, s2, off);
    }
    if (l == 0) { wsum1[w] = s1; wsum2[w] = s2; }
    __syncthreads();
    if (tid == 0) {
        float mc = 0.f, ss = 0.f;
        for (int wi = 0; wi < 8; wi++) { mc += wsum1[wi]; ss += wsum2[wi]; }
        g_mc[bn]  = mc;
        g_avg[bn] = (mc > 0.f) ? ss / (float)T_ : 0.f;
    }
}

// ---------------------------------------------------------------------------
// Kernel 4: top-5 + output formatting. grid (B, K_TOP) — each CTA computes
// the cheap top-5 redundantly and writes slice k; k==0 also writes
// id/score/match_counts.
// ---------------------------------------------------------------------------
__global__ void finalize_kernel(float* __restrict__ out) {
    int b = blockIdx.x;
    int k = blockIdx.y;
    int tid = threadIdx.x;
    __shared__ int   sid[K_TOP];
    __shared__ float sval[K_TOP];

    if (tid == 0) {
        bool used[N_];
        for (int n = 0; n < N_; n++) used[n] = false;
        for (int kk = 0; kk < K_TOP; kk++) {
            float best = -1.f; int bi = 0; bool found = false;
            for (int n = 0; n < N_; n++) {
                float v = g_avg[b * N_ + n];
                if (!used[n] && (!found || v > best)) {
                    best = v; bi = n; found = true;
                }
            }
            used[bi] = true; sid[kk] = bi; sval[kk] = best;
        }
    }
    __syncthreads();

    const int OFF_SP   = 2 * B_ * K_TOP;
    const int OFF_TP   = OFF_SP + B_ * K_TOP * T_;
    const int OFF_SRCP = OFF_TP + B_ * K_TOP * T_ * 2;
    const int OFF_MC   = OFF_SRCP + B_ * K_TOP * T_ * 2;

    if (k == 0) {
        if (tid < K_TOP) {
            out[b * K_TOP + tid] = (float)sid[tid];
            out[B_ * K_TOP + b * K_TOP + tid] = sval[tid];
        }
        if (tid < N_) out[OFF_MC + b * N_ + tid] = g_mc[b * N_ + tid];
    }

    int t = tid;
    int bnsel = b * N_ + sid[k];
    float sc = g_scoret[bnsel * T_ + t];
    float m  = g_maskall[bnsel * T_ + t];
    int   it = g_idxt[bnsel * T_ + t];
    int base = (b * K_TOP + k) * T_ + t;
    out[OFF_SP + base] = sc;
    bool nz = (m != 0.f);
    out[OFF_TP + base * 2 + 0]   = nz ? (float)(t & 15)  : -1.f;
    out[OFF_TP + base * 2 + 1]   = nz ? (float)(t >> 4)  : -1.f;
    out[OFF_SRCP + base * 2 + 0] = nz ? (float)(it & 15) : -1.f;
    out[OFF_SRCP + base * 2 + 1] = nz ? (float)(it >> 4) : -1.f;
}

// ---------------------------------------------------------------------------
extern "C" void kernel_launch(void* const* d_in, const int* in_sizes, int n_in,
                              void* d_out, int out_size) {
    const float* sf   = (const float*)d_in[0];  // (B,N,C,P,P)
    const float* tf   = (const float*)d_in[1];  // (B,C,P,P)
    const float* srcm = (const float*)d_in[2];  // (B,N,P,P)
    const float* tarm = (const float*)d_in[3];  // (B,P,P)

    cudaFuncSetAttribute(sim_hmma_kernel,
                         cudaFuncAttributeMaxDynamicSharedMemorySize, SMEM_DYN);

    dim3 gp(B_ * N_ + B_, T_ / 32);
    prep_kernel<<<gp, 256>>>(sf, tf, srcm, tarm);
    dim3 gs(B_ * N_, 4);
    sim_hmma_kernel<<<gs, 256, SMEM_DYN>>>();
    post_kernel<<<B_ * N_, 256>>>(srcm, tarm);
    dim3 gf(B_, K_TOP);
    finalize_kernel<<<gf, 256>>>((float*)d_out);
}